// round 16
// baseline (speedup 1.0000x reference)
#include <cuda_runtime.h>
#include <cuda_fp16.h>
#include <math.h>

#define NN 50000
#define EE 1000000
#define FIN 512
#define HID 128
#define HEADS 8
#define SCAN_BLKS 25   // ceil(NN / 2048)

// ---------------- device scratch ----------------
__device__ float  g_xp[NN * HID];            // projected features (fp32, for attdot)
__device__ __half g_xph[NN * HID];           // projected features (fp16, for gather)
__device__ float  g_asrc[2][NN * HEADS];
__device__ float  g_adst[2][NN * HEADS];
__device__ int    g_deg[2][NN];
__device__ int    g_rowptr[2][NN + 1];
__device__ int    g_cursor[2][NN];
__device__ int    g_csr[2][EE];
__device__ int    g_bsum[2][32];
__device__ float  g_outm[2][NN * HID];
__device__ float  g_colsum[2][HID];
__device__ float  g_beta[2];

__device__ __forceinline__ float to_tf32(float x) {
    float r;
    asm("cvt.rna.tf32.f32 %0, %1;" : "=f"(r) : "f"(x));
    return r;
}

__device__ __forceinline__ void mma_tf32(float& d0, float& d1, float& d2, float& d3,
                                         unsigned a0, unsigned a1, unsigned a2, unsigned a3,
                                         unsigned b0, unsigned b1) {
    asm volatile(
        "mma.sync.aligned.m16n8k8.row.col.f32.tf32.tf32.f32 "
        "{%0,%1,%2,%3}, {%4,%5,%6,%7}, {%8,%9}, {%0,%1,%2,%3};"
        : "+f"(d0), "+f"(d1), "+f"(d2), "+f"(d3)
        : "r"(a0), "r"(a1), "r"(a2), "r"(a3), "r"(b0), "r"(b1));
}

// =====================================================================
// Projection GEMM: KT=16 cp.async 2-stage, 2 CTAs/SM.
// A smem: [128][20], B smem: [16][136]; stage = 4736 floats = 18944 B.
// =====================================================================
#define KT_P 16
#define AST_P 20
#define BST 136
#define AFL_P (128 * AST_P)
#define STG_P (AFL_P + KT_P * BST)
#define PROJ_SMEM (2 * STG_P * 4)

__device__ __forceinline__ void cp_stage_p(const float* __restrict__ A,
                                           const float* __restrict__ W,
                                           float* As, float* Bs,
                                           int m0, int t, int k0) {
#pragma unroll
    for (int l = 0; l < 2; l++) {
        int p = t + l * 256;                  // 512 float4 for A (128x16)
        int row = p >> 2, c4 = (p & 3) * 4;
        int gr = m0 + row;
        unsigned dst = (unsigned)__cvta_generic_to_shared(As + row * AST_P + c4);
        const float* src = A + (size_t)gr * FIN + k0 + c4;
        int sz = (gr < NN) ? 16 : 0;
        asm volatile("cp.async.cg.shared.global [%0],[%1],16,%2;\n"
                     :: "r"(dst), "l"(src), "r"(sz));
    }
#pragma unroll
    for (int l = 0; l < 2; l++) {
        int p = t + l * 256;                  // 512 float4 for B (16x128)
        int kr = p >> 5, c4 = (p & 31) * 4;
        unsigned dst = (unsigned)__cvta_generic_to_shared(Bs + kr * BST + c4);
        const float* src = W + (size_t)(k0 + kr) * HID + c4;
        asm volatile("cp.async.cg.shared.global [%0],[%1],16,16;\n"
                     :: "r"(dst), "l"(src));
    }
    asm volatile("cp.async.commit_group;\n");
}

__global__ __launch_bounds__(256, 2) void k_gemm_proj(const float* __restrict__ A,
                                                      const float* __restrict__ W,
                                                      const float* __restrict__ bias) {
    extern __shared__ float sm[];
    const int m0 = blockIdx.x * 128;
    const int t = threadIdx.x;
    const int lane = t & 31, wid = t >> 5;
    const int wm = wid >> 2, wn = wid & 3;
    const int qr = lane >> 2, qc = lane & 3;

    float acc[4][4][4];
#pragma unroll
    for (int i = 0; i < 4; i++)
#pragma unroll
        for (int j = 0; j < 4; j++)
#pragma unroll
            for (int v = 0; v < 4; v++) acc[i][j][v] = 0.f;

    cp_stage_p(A, W, sm, sm + AFL_P, m0, t, 0);
    int buf = 0;
    for (int k0 = 0; k0 < FIN; k0 += KT_P) {
        asm volatile("cp.async.wait_group 0;\n");
        __syncthreads();
        if (k0 + KT_P < FIN)
            cp_stage_p(A, W, sm + (buf ^ 1) * STG_P, sm + (buf ^ 1) * STG_P + AFL_P,
                       m0, t, k0 + KT_P);
        const float* As = sm + buf * STG_P;
        const float* Bs = sm + buf * STG_P + AFL_P;
#pragma unroll
        for (int kk = 0; kk < KT_P; kk += 8) {
            unsigned af[4][4], bf[4][2];
#pragma unroll
            for (int i = 0; i < 4; i++) {
                int r = wm * 64 + i * 16 + qr;
                af[i][0] = __float_as_uint(to_tf32(As[r * AST_P + kk + qc]));
                af[i][1] = __float_as_uint(to_tf32(As[(r + 8) * AST_P + kk + qc]));
                af[i][2] = __float_as_uint(to_tf32(As[r * AST_P + kk + 4 + qc]));
                af[i][3] = __float_as_uint(to_tf32(As[(r + 8) * AST_P + kk + 4 + qc]));
            }
#pragma unroll
            for (int j = 0; j < 4; j++) {
                int c = wn * 32 + j * 8 + qr;
                bf[j][0] = __float_as_uint(to_tf32(Bs[(kk + qc) * BST + c]));
                bf[j][1] = __float_as_uint(to_tf32(Bs[(kk + 4 + qc) * BST + c]));
            }
#pragma unroll
            for (int i = 0; i < 4; i++)
#pragma unroll
                for (int j = 0; j < 4; j++)
                    mma_tf32(acc[i][j][0], acc[i][j][1], acc[i][j][2], acc[i][j][3],
                             af[i][0], af[i][1], af[i][2], af[i][3], bf[j][0], bf[j][1]);
        }
        buf ^= 1;
    }
    // epilogue: + bias, store fp32 + fp16
    float bi[4][2];
#pragma unroll
    for (int j = 0; j < 4; j++) {
        int c = wn * 32 + j * 8 + qc * 2;
        bi[j][0] = bias[c]; bi[j][1] = bias[c + 1];
    }
#pragma unroll
    for (int i = 0; i < 4; i++) {
        int r0 = m0 + wm * 64 + i * 16 + qr;
#pragma unroll
        for (int j = 0; j < 4; j++) {
            int c = wn * 32 + j * 8 + qc * 2;
            if (r0 < NN) {
                float2 v = make_float2(acc[i][j][0] + bi[j][0], acc[i][j][1] + bi[j][1]);
                *(float2*)(g_xp + (size_t)r0 * HID + c) = v;
                *(__half2*)(g_xph + (size_t)r0 * HID + c) = __floats2half2_rn(v.x, v.y);
            }
            if (r0 + 8 < NN) {
                float2 v = make_float2(acc[i][j][2] + bi[j][0], acc[i][j][3] + bi[j][1]);
                *(float2*)(g_xp + (size_t)(r0 + 8) * HID + c) = v;
                *(__half2*)(g_xph + (size_t)(r0 + 8) * HID + c) = __floats2half2_rn(v.x, v.y);
            }
        }
    }
}

// =====================================================================
// Semantic GEMM: KT=32 cp.async 2-stage pipeline + tanh colsum epilogue.
// A smem: [128][36], B smem: [32][136]; stage = 8960 floats; 71680 B total.
// =====================================================================
#define KT_T 32
#define AST_T 36
#define AFL_T (128 * AST_T)
#define STG_T (AFL_T + KT_T * BST)
#define TANH_SMEM (2 * STG_T * 4)

__device__ __forceinline__ void cp_stage_t(const float* __restrict__ A,
                                           const float* __restrict__ W,
                                           float* As, float* Bs,
                                           int m0, int t, int k0) {
#pragma unroll
    for (int l = 0; l < 4; l++) {
        int p = t + l * 256;
        int row = p >> 3, c4 = (p & 7) * 4;
        int gr = m0 + row;
        unsigned dst = (unsigned)__cvta_generic_to_shared(As + row * AST_T + c4);
        const float* src = A + (size_t)gr * HID + k0 + c4;
        int sz = (gr < NN) ? 16 : 0;
        asm volatile("cp.async.cg.shared.global [%0],[%1],16,%2;\n"
                     :: "r"(dst), "l"(src), "r"(sz));
    }
#pragma unroll
    for (int l = 0; l < 4; l++) {
        int p = t + l * 256;
        int kr = p >> 5, c4 = (p & 31) * 4;
        unsigned dst = (unsigned)__cvta_generic_to_shared(Bs + kr * BST + c4);
        const float* src = W + (size_t)(k0 + kr) * HID + c4;
        asm volatile("cp.async.cg.shared.global [%0],[%1],16,16;\n"
                     :: "r"(dst), "l"(src));
    }
    asm volatile("cp.async.commit_group;\n");
}

__global__ __launch_bounds__(256) void k_gemm_tanh(const float* __restrict__ W,
                                                   const float* __restrict__ bias) {
    extern __shared__ float sm[];
    __shared__ float cs[HID];
    const int m0 = blockIdx.x * 128;
    const int meta = blockIdx.y;
    const float* __restrict__ A = g_outm[meta];
    const int t = threadIdx.x;
    const int lane = t & 31, wid = t >> 5;
    const int wm = wid >> 2, wn = wid & 3;
    const int qr = lane >> 2, qc = lane & 3;

    if (t < HID) cs[t] = 0.f;

    float acc[4][4][4];
#pragma unroll
    for (int i = 0; i < 4; i++)
#pragma unroll
        for (int j = 0; j < 4; j++)
#pragma unroll
            for (int v = 0; v < 4; v++) acc[i][j][v] = 0.f;

    cp_stage_t(A, W, sm, sm + AFL_T, m0, t, 0);
    int buf = 0;
#pragma unroll
    for (int k0 = 0; k0 < HID; k0 += KT_T) {
        asm volatile("cp.async.wait_group 0;\n");
        __syncthreads();
        if (k0 + KT_T < HID)
            cp_stage_t(A, W, sm + (buf ^ 1) * STG_T, sm + (buf ^ 1) * STG_T + AFL_T,
                       m0, t, k0 + KT_T);
        const float* As = sm + buf * STG_T;
        const float* Bs = sm + buf * STG_T + AFL_T;
#pragma unroll
        for (int kk = 0; kk < KT_T; kk += 8) {
            unsigned af[4][4], bf[4][2];
#pragma unroll
            for (int i = 0; i < 4; i++) {
                int r = wm * 64 + i * 16 + qr;
                af[i][0] = __float_as_uint(to_tf32(As[r * AST_T + kk + qc]));
                af[i][1] = __float_as_uint(to_tf32(As[(r + 8) * AST_T + kk + qc]));
                af[i][2] = __float_as_uint(to_tf32(As[r * AST_T + kk + 4 + qc]));
                af[i][3] = __float_as_uint(to_tf32(As[(r + 8) * AST_T + kk + 4 + qc]));
            }
#pragma unroll
            for (int j = 0; j < 4; j++) {
                int c = wn * 32 + j * 8 + qr;
                bf[j][0] = __float_as_uint(to_tf32(Bs[(kk + qc) * BST + c]));
                bf[j][1] = __float_as_uint(to_tf32(Bs[(kk + 4 + qc) * BST + c]));
            }
#pragma unroll
            for (int i = 0; i < 4; i++)
#pragma unroll
                for (int j = 0; j < 4; j++)
                    mma_tf32(acc[i][j][0], acc[i][j][1], acc[i][j][2], acc[i][j][3],
                             af[i][0], af[i][1], af[i][2], af[i][3], bf[j][0], bf[j][1]);
        }
        buf ^= 1;
    }
    __syncthreads();
#pragma unroll
    for (int j = 0; j < 4; j++) {
        int c = wn * 32 + j * 8 + qc * 2;
        float b0 = bias[c], b1 = bias[c + 1];
        float s0 = 0.f, s1 = 0.f;
#pragma unroll
        for (int i = 0; i < 4; i++) {
            int r0 = m0 + wm * 64 + i * 16 + qr;
            if (r0 < NN)     { s0 += tanhf(acc[i][j][0] + b0); s1 += tanhf(acc[i][j][1] + b1); }
            if (r0 + 8 < NN) { s0 += tanhf(acc[i][j][2] + b0); s1 += tanhf(acc[i][j][3] + b1); }
        }
        atomicAdd(&cs[c], s0);
        atomicAdd(&cs[c + 1], s1);
    }
    __syncthreads();
    if (t < HID) atomicAdd(&g_colsum[meta][t], cs[t]);
}

// ---------------- attention dot products ----------------
__global__ void k_attdot(const float* __restrict__ s0, const float* __restrict__ d0,
                         const float* __restrict__ s1, const float* __restrict__ d1) {
    int i = blockIdx.x * blockDim.x + threadIdx.x;   // n*8 + h
    if (i >= NN * HEADS) return;
    int h = i & 7;
    const float* xp = g_xp + (size_t)i * 16;
    float r0 = 0.f, r1 = 0.f, r2 = 0.f, r3 = 0.f;
#pragma unroll
    for (int d = 0; d < 16; d++) {
        float xv = xp[d];
        r0 += xv * s0[h * 16 + d];
        r1 += xv * d0[h * 16 + d];
        r2 += xv * s1[h * 16 + d];
        r3 += xv * d1[h * 16 + d];
    }
    g_asrc[0][i] = r0; g_adst[0][i] = r1;
    g_asrc[1][i] = r2; g_adst[1][i] = r3;
}

// ---------------- CSR build: 2 INDEPENDENT edges per thread ----------------
__global__ void k_deg(const int* __restrict__ e0, const int* __restrict__ e1) {
    int i = blockIdx.x * blockDim.x + threadIdx.x;
    if (i >= EE / 2) return;
    int m = blockIdx.y;
    const int* ei = m ? e1 : e0;
    int dA = ei[EE + i];
    int dB = ei[EE + i + EE / 2];
    atomicAdd(&g_deg[m][dA], 1);
    atomicAdd(&g_deg[m][dB], 1);
}

// ---- 3-phase parallel scan over g_deg -> g_rowptr/g_cursor ----
__global__ __launch_bounds__(256) void k_scan1() {
    int m = blockIdx.y, b = blockIdx.x, t = threadIdx.x;
    int base = b * 2048 + t * 8;
    int v[8];
    int s = 0;
#pragma unroll
    for (int i = 0; i < 8; i++) {
        v[i] = (base + i < NN) ? g_deg[m][base + i] : 0;
        s += v[i];
    }
    __shared__ int sh[256];
    sh[t] = s;
    __syncthreads();
#pragma unroll
    for (int off = 1; off < 256; off <<= 1) {
        int x = (t >= off) ? sh[t - off] : 0;
        __syncthreads();
        sh[t] += x;
        __syncthreads();
    }
    int run = (t == 0) ? 0 : sh[t - 1];
    if (t == 255) g_bsum[m][b] = sh[255];
#pragma unroll
    for (int i = 0; i < 8; i++) {
        if (base + i < NN) g_rowptr[m][base + i] = run;
        run += v[i];
    }
}

__global__ void k_scan2() {
    int m = blockIdx.x, t = threadIdx.x;   // 32 threads
    int v = (t < SCAN_BLKS) ? g_bsum[m][t] : 0;
    int orig = v;
#pragma unroll
    for (int off = 1; off < 32; off <<= 1) {
        int x = __shfl_up_sync(0xffffffffu, v, off);
        if (t >= off) v += x;
    }
    if (t < SCAN_BLKS) g_bsum[m][t] = v - orig;   // exclusive
    if (t == SCAN_BLKS - 1) g_rowptr[m][NN] = v;  // total
}

__global__ __launch_bounds__(256) void k_scan3() {
    int m = blockIdx.y, b = blockIdx.x, t = threadIdx.x;
    int off = g_bsum[m][b];
    int base = b * 2048 + t * 8;
#pragma unroll
    for (int i = 0; i < 8; i++) {
        int idx = base + i;
        if (idx < NN) {
            int r = g_rowptr[m][idx] + off;
            g_rowptr[m][idx] = r;
            g_cursor[m][idx] = r;
        }
    }
}

__global__ void k_fill(const int* __restrict__ e0, const int* __restrict__ e1) {
    int i = blockIdx.x * blockDim.x + threadIdx.x;
    if (i >= EE / 2) return;
    int m = blockIdx.y;
    const int* ei = m ? e1 : e0;
    int sA = ei[i],          dA = ei[EE + i];
    int sB = ei[i + EE / 2], dB = ei[EE + i + EE / 2];
    int pA = atomicAdd(&g_cursor[m][dA], 1);
    int pB = atomicAdd(&g_cursor[m][dB], 1);
    g_csr[m][pA] = sA;
    g_csr[m][pB] = sB;
}

// ---------------- fused softmax + aggregation (fp16 gather, 2x unroll) ----------------
__global__ __launch_bounds__(256) void k_agg() {
    int warp = (blockIdx.x * blockDim.x + threadIdx.x) >> 5;
    if (warp >= NN) return;
    int m = blockIdx.y;
    int lane = threadIdx.x & 31;
    int h = lane >> 2;
    int n = warp;
    float adst = g_adst[m][n * 8 + h];
    const float* __restrict__ asrc = g_asrc[m];
    const int* __restrict__ csr = g_csr[m];
    const uint2* __restrict__ xph = (const uint2*)g_xph;  // row stride = 32 uint2
    int j = g_rowptr[m][n], j1 = g_rowptr[m][n + 1];
    float ax = 0.f, ay = 0.f, az = 0.f, aw = 0.f, den = 0.f;
    for (; j + 1 < j1; j += 2) {
        int s0 = csr[j], s1 = csr[j + 1];
        float al0 = asrc[s0 * 8 + h] + adst;
        float al1 = asrc[s1 * 8 + h] + adst;
        uint2 u0 = xph[s0 * 32 + lane];
        uint2 u1 = xph[s1 * 32 + lane];
        al0 = (al0 > 0.f) ? al0 : 0.2f * al0;
        al1 = (al1 > 0.f) ? al1 : 0.2f * al1;
        float e0 = __expf(al0), e1 = __expf(al1);
        float2 f00 = __half22float2(*(__half2*)&u0.x);
        float2 f01 = __half22float2(*(__half2*)&u0.y);
        float2 f10 = __half22float2(*(__half2*)&u1.x);
        float2 f11 = __half22float2(*(__half2*)&u1.y);
        ax += e0 * f00.x; ay += e0 * f00.y; az += e0 * f01.x; aw += e0 * f01.y; den += e0;
        ax += e1 * f10.x; ay += e1 * f10.y; az += e1 * f11.x; aw += e1 * f11.y; den += e1;
    }
    if (j < j1) {
        int s0 = csr[j];
        float al0 = asrc[s0 * 8 + h] + adst;
        uint2 u0 = xph[s0 * 32 + lane];
        al0 = (al0 > 0.f) ? al0 : 0.2f * al0;
        float e0 = __expf(al0);
        float2 f00 = __half22float2(*(__half2*)&u0.x);
        float2 f01 = __half22float2(*(__half2*)&u0.y);
        ax += e0 * f00.x; ay += e0 * f00.y; az += e0 * f01.x; aw += e0 * f01.y; den += e0;
    }
    float inv = 1.f / (den + 1e-16f);
    float4 r;
    r.x = fmaxf(ax * inv, 0.f);
    r.y = fmaxf(ay * inv, 0.f);
    r.z = fmaxf(az * inv, 0.f);
    r.w = fmaxf(aw * inv, 0.f);
    *(float4*)(g_outm[m] + (size_t)n * HID + lane * 4) = r;
}

// ---------------- semantic softmax (beta) ----------------
__global__ void k_sem(const float* __restrict__ q) {
    __shared__ float s0[128], s1[128];
    int t = threadIdx.x;
    float qt = q[t];
    s0[t] = g_colsum[0][t] * (1.f / NN) * qt;
    s1[t] = g_colsum[1][t] * (1.f / NN) * qt;
    __syncthreads();
    for (int off = 64; off; off >>= 1) {
        if (t < off) { s0[t] += s0[t + off]; s1[t] += s1[t + off]; }
        __syncthreads();
    }
    if (t == 0) {
        float a = s0[0], b = s1[0];
        float mx = fmaxf(a, b);
        float ea = __expf(a - mx), eb = __expf(b - mx);
        float inv = 1.f / (ea + eb);
        g_beta[0] = ea * inv;
        g_beta[1] = eb * inv;
    }
}

// ---------------- final head ----------------
__global__ __launch_bounds__(256) void k_final(const float* __restrict__ Wl,
                                               const float* __restrict__ bl,
                                               float* __restrict__ out) {
    int warp = (blockIdx.x * blockDim.x + threadIdx.x) >> 5;
    if (warp >= NN) return;
    int lane = threadIdx.x & 31;
    float b0 = g_beta[0], b1 = g_beta[1];
    float p0 = 0.f, p1 = 0.f, p2 = 0.f;
#pragma unroll
    for (int r = 0; r < 4; r++) {
        int c = lane + r * 32;
        float f = b0 * g_outm[0][(size_t)warp * HID + c] + b1 * g_outm[1][(size_t)warp * HID + c];
        p0 += f * Wl[c * 3 + 0];
        p1 += f * Wl[c * 3 + 1];
        p2 += f * Wl[c * 3 + 2];
    }
#pragma unroll
    for (int off = 16; off; off >>= 1) {
        p0 += __shfl_down_sync(0xffffffffu, p0, off);
        p1 += __shfl_down_sync(0xffffffffu, p1, off);
        p2 += __shfl_down_sync(0xffffffffu, p2, off);
    }
    if (lane == 0) {
        out[warp * 3 + 0] = p0 + bl[0];
        out[warp * 3 + 1] = p1 + bl[1];
        out[warp * 3 + 2] = p2 + bl[2];
    }
}

// ---------------- launch ----------------
extern "C" void kernel_launch(void* const* d_in, const int* in_sizes, int n_in,
                              void* d_out, int out_size) {
    const float* x      = (const float*)d_in[0];
    const int*   e0     = (const int*)d_in[1];
    const int*   e1     = (const int*)d_in[2];
    const float* W_proj = (const float*)d_in[3];
    const float* b_proj = (const float*)d_in[4];
    const float* as0    = (const float*)d_in[5];
    const float* ad0    = (const float*)d_in[6];
    const float* as1    = (const float*)d_in[7];
    const float* ad1    = (const float*)d_in[8];
    const float* Wk     = (const float*)d_in[9];
    const float* bk     = (const float*)d_in[10];
    const float* q      = (const float*)d_in[11];
    const float* W_lin  = (const float*)d_in[12];
    const float* b_lin  = (const float*)d_in[13];
    float* out = (float*)d_out;

    static void* p_deg = nullptr;
    static void* p_colsum = nullptr;
    if (!p_deg) {
        cudaGetSymbolAddress(&p_deg, g_deg);
        cudaGetSymbolAddress(&p_colsum, g_colsum);
        cudaFuncSetAttribute(k_gemm_proj, cudaFuncAttributeMaxDynamicSharedMemorySize, PROJ_SMEM);
        cudaFuncSetAttribute(k_gemm_tanh, cudaFuncAttributeMaxDynamicSharedMemorySize, TANH_SMEM);
    }

    cudaMemsetAsync(p_deg, 0, 2 * NN * sizeof(int), 0);
    cudaMemsetAsync(p_colsum, 0, 2 * HID * sizeof(float), 0);

    k_gemm_proj<<<(NN + 127) / 128, 256, PROJ_SMEM>>>(x, W_proj, b_proj);
    k_attdot<<<(NN * HEADS + 255) / 256, 256>>>(as0, ad0, as1, ad1);
    dim3 geh((EE / 2 + 255) / 256, 2);
    k_deg<<<geh, 256>>>(e0, e1);
    k_scan1<<<dim3(SCAN_BLKS, 2), 256>>>();
    k_scan2<<<2, 32>>>();
    k_scan3<<<dim3(SCAN_BLKS, 2), 256>>>();
    k_fill<<<geh, 256>>>(e0, e1);
    k_agg<<<dim3((NN + 7) / 8, 2), 256>>>();
    k_gemm_tanh<<<dim3((NN + 127) / 128, 2), 256, TANH_SMEM>>>(Wk, bk);
    k_sem<<<1, 128>>>(q);
    k_final<<<(NN + 7) / 8, 256>>>(W_lin, b_lin, out);
}

// round 17
// speedup vs baseline: 1.1041x; 1.1041x over previous
#include <cuda_runtime.h>
#include <cuda_fp16.h>
#include <math.h>

#define NN 50000
#define EE 1000000
#define FIN 512
#define HID 128
#define HEADS 8
#define KT 32
#define SCAN_BLKS 25   // ceil(NN / 2048)

// ---------------- device scratch ----------------
__device__ float  g_xp[NN * HID];            // projected features (fp32, for attdot)
__device__ __half g_xph[NN * HID];           // projected features (fp16, for gather)
__device__ float  g_asrc[2][NN * HEADS];
__device__ float  g_adst[2][NN * HEADS];
__device__ int    g_deg[2][NN];
__device__ int    g_rowptr[2][NN + 1];
__device__ int    g_cursor[2][NN];
__device__ int    g_csr[2][EE];
__device__ int    g_bsum[2][32];
__device__ float  g_outm[2][NN * HID];
__device__ float  g_colsum[2][HID];
__device__ float  g_beta[2];

__device__ __forceinline__ float to_tf32(float x) {
    float r;
    asm("cvt.rna.tf32.f32 %0, %1;" : "=f"(r) : "f"(x));
    return r;
}

__device__ __forceinline__ void mma_tf32(float& d0, float& d1, float& d2, float& d3,
                                         unsigned a0, unsigned a1, unsigned a2, unsigned a3,
                                         unsigned b0, unsigned b1) {
    asm volatile(
        "mma.sync.aligned.m16n8k8.row.col.f32.tf32.tf32.f32 "
        "{%0,%1,%2,%3}, {%4,%5,%6,%7}, {%8,%9}, {%0,%1,%2,%3};"
        : "+f"(d0), "+f"(d1), "+f"(d2), "+f"(d3)
        : "r"(a0), "r"(a1), "r"(a2), "r"(a3), "r"(b0), "r"(b1));
}

// =====================================================================
// cp.async 2-stage TF32 GEMM (projection).
// A smem: [128][36], B smem: [32][136]; stage = 8960 floats, 2 stages = 71680 B.
// =====================================================================
#define ASTRIDE 36
#define BSTRIDE 136
#define AFLOATS (128 * ASTRIDE)
#define STG (AFLOATS + KT * BSTRIDE)
#define PROJ_SMEM (2 * STG * 4)

__device__ __forceinline__ void cp_stage_proj(const float* __restrict__ A,
                                              const float* __restrict__ W,
                                              float* As, float* Bs,
                                              int m0, int t, int k0) {
#pragma unroll
    for (int l = 0; l < 4; l++) {
        int p = t + l * 256;
        int row = p >> 3, c4 = (p & 7) * 4;
        int gr = m0 + row;
        unsigned dst = (unsigned)__cvta_generic_to_shared(As + row * ASTRIDE + c4);
        const float* src = A + (size_t)gr * FIN + k0 + c4;
        int sz = (gr < NN) ? 16 : 0;
        asm volatile("cp.async.cg.shared.global [%0],[%1],16,%2;\n"
                     :: "r"(dst), "l"(src), "r"(sz));
    }
#pragma unroll
    for (int l = 0; l < 4; l++) {
        int p = t + l * 256;
        int kr = p >> 5, c4 = (p & 31) * 4;
        unsigned dst = (unsigned)__cvta_generic_to_shared(Bs + kr * BSTRIDE + c4);
        const float* src = W + (size_t)(k0 + kr) * HID + c4;
        asm volatile("cp.async.cg.shared.global [%0],[%1],16,16;\n"
                     :: "r"(dst), "l"(src));
    }
    asm volatile("cp.async.commit_group;\n");
}

__global__ __launch_bounds__(256) void k_gemm_proj(const float* __restrict__ A,
                                                   const float* __restrict__ W,
                                                   const float* __restrict__ bias) {
    extern __shared__ float sm[];
    const int m0 = blockIdx.x * 128;
    const int t = threadIdx.x;
    const int lane = t & 31, wid = t >> 5;
    const int wm = wid >> 2, wn = wid & 3;
    const int qr = lane >> 2, qc = lane & 3;

    float acc[4][4][4];
#pragma unroll
    for (int i = 0; i < 4; i++)
#pragma unroll
        for (int j = 0; j < 4; j++)
#pragma unroll
            for (int v = 0; v < 4; v++) acc[i][j][v] = 0.f;

    cp_stage_proj(A, W, sm, sm + AFLOATS, m0, t, 0);
    int buf = 0;
    for (int k0 = 0; k0 < FIN; k0 += KT) {
        asm volatile("cp.async.wait_group 0;\n");
        __syncthreads();
        if (k0 + KT < FIN)
            cp_stage_proj(A, W, sm + (buf ^ 1) * STG, sm + (buf ^ 1) * STG + AFLOATS,
                          m0, t, k0 + KT);
        const float* As = sm + buf * STG;
        const float* Bs = sm + buf * STG + AFLOATS;
#pragma unroll
        for (int kk = 0; kk < KT; kk += 8) {
            unsigned af[4][4], bf[4][2];
#pragma unroll
            for (int i = 0; i < 4; i++) {
                int r = wm * 64 + i * 16 + qr;
                af[i][0] = __float_as_uint(to_tf32(As[r * ASTRIDE + kk + qc]));
                af[i][1] = __float_as_uint(to_tf32(As[(r + 8) * ASTRIDE + kk + qc]));
                af[i][2] = __float_as_uint(to_tf32(As[r * ASTRIDE + kk + 4 + qc]));
                af[i][3] = __float_as_uint(to_tf32(As[(r + 8) * ASTRIDE + kk + 4 + qc]));
            }
#pragma unroll
            for (int j = 0; j < 4; j++) {
                int c = wn * 32 + j * 8 + qr;
                bf[j][0] = __float_as_uint(to_tf32(Bs[(kk + qc) * BSTRIDE + c]));
                bf[j][1] = __float_as_uint(to_tf32(Bs[(kk + 4 + qc) * BSTRIDE + c]));
            }
#pragma unroll
            for (int i = 0; i < 4; i++)
#pragma unroll
                for (int j = 0; j < 4; j++)
                    mma_tf32(acc[i][j][0], acc[i][j][1], acc[i][j][2], acc[i][j][3],
                             af[i][0], af[i][1], af[i][2], af[i][3], bf[j][0], bf[j][1]);
        }
        buf ^= 1;
    }
    // epilogue: + bias, store fp32 + fp16
    float bi[4][2];
#pragma unroll
    for (int j = 0; j < 4; j++) {
        int c = wn * 32 + j * 8 + qc * 2;
        bi[j][0] = bias[c]; bi[j][1] = bias[c + 1];
    }
#pragma unroll
    for (int i = 0; i < 4; i++) {
        int r0 = m0 + wm * 64 + i * 16 + qr;
#pragma unroll
        for (int j = 0; j < 4; j++) {
            int c = wn * 32 + j * 8 + qc * 2;
            if (r0 < NN) {
                float2 v = make_float2(acc[i][j][0] + bi[j][0], acc[i][j][1] + bi[j][1]);
                *(float2*)(g_xp + (size_t)r0 * HID + c) = v;
                *(__half2*)(g_xph + (size_t)r0 * HID + c) = __floats2half2_rn(v.x, v.y);
            }
            if (r0 + 8 < NN) {
                float2 v = make_float2(acc[i][j][2] + bi[j][0], acc[i][j][3] + bi[j][1]);
                *(float2*)(g_xp + (size_t)(r0 + 8) * HID + c) = v;
                *(__half2*)(g_xph + (size_t)(r0 + 8) * HID + c) = __floats2half2_rn(v.x, v.y);
            }
        }
    }
}

// ---- semantic GEMM (single-buffered, proven config): colsum_m = sum_n tanh(o_m @ Wk + bk) ----
__global__ __launch_bounds__(256) void k_gemm_tanh(const float* __restrict__ W,
                                                   const float* __restrict__ bias) {
    __shared__ float As[128][36];
    __shared__ float Bs[KT][132];
    __shared__ float cs[HID];
    const int m0 = blockIdx.x * 128;
    const int meta = blockIdx.y;
    const float* __restrict__ A = g_outm[meta];
    const int t = threadIdx.x;
    const int lane = t & 31, wid = t >> 5;
    const int wm = wid >> 2, wn = wid & 3;
    const int qr = lane >> 2, qc = lane & 3;

    if (t < HID) cs[t] = 0.f;

    float acc[4][4][4];
#pragma unroll
    for (int i = 0; i < 4; i++)
#pragma unroll
        for (int j = 0; j < 4; j++)
#pragma unroll
            for (int v = 0; v < 4; v++) acc[i][j][v] = 0.f;

    for (int k0 = 0; k0 < HID; k0 += KT) {
#pragma unroll
        for (int l = 0; l < 4; l++) {
            int p = t + l * 256;
            int row = p >> 3, c4 = (p & 7) * 4;
            int gr = m0 + row;
            float4 v = make_float4(0.f, 0.f, 0.f, 0.f);
            if (gr < NN) v = *(const float4*)(A + (size_t)gr * HID + k0 + c4);
            As[row][c4 + 0] = to_tf32(v.x); As[row][c4 + 1] = to_tf32(v.y);
            As[row][c4 + 2] = to_tf32(v.z); As[row][c4 + 3] = to_tf32(v.w);
        }
#pragma unroll
        for (int l = 0; l < 4; l++) {
            int p = t + l * 256;
            int kr = p >> 5, c4 = (p & 31) * 4;
            float4 v = *(const float4*)(W + (size_t)(k0 + kr) * HID + c4);
            Bs[kr][c4 + 0] = to_tf32(v.x); Bs[kr][c4 + 1] = to_tf32(v.y);
            Bs[kr][c4 + 2] = to_tf32(v.z); Bs[kr][c4 + 3] = to_tf32(v.w);
        }
        __syncthreads();
#pragma unroll
        for (int kk = 0; kk < KT; kk += 8) {
            unsigned af[4][4], bf[4][2];
#pragma unroll
            for (int i = 0; i < 4; i++) {
                int r = wm * 64 + i * 16 + qr;
                af[i][0] = __float_as_uint(As[r][kk + qc]);
                af[i][1] = __float_as_uint(As[r + 8][kk + qc]);
                af[i][2] = __float_as_uint(As[r][kk + 4 + qc]);
                af[i][3] = __float_as_uint(As[r + 8][kk + 4 + qc]);
            }
#pragma unroll
            for (int j = 0; j < 4; j++) {
                int c = wn * 32 + j * 8 + qr;
                bf[j][0] = __float_as_uint(Bs[kk + qc][c]);
                bf[j][1] = __float_as_uint(Bs[kk + 4 + qc][c]);
            }
#pragma unroll
            for (int i = 0; i < 4; i++)
#pragma unroll
                for (int j = 0; j < 4; j++)
                    mma_tf32(acc[i][j][0], acc[i][j][1], acc[i][j][2], acc[i][j][3],
                             af[i][0], af[i][1], af[i][2], af[i][3], bf[j][0], bf[j][1]);
        }
        __syncthreads();
    }
#pragma unroll
    for (int j = 0; j < 4; j++) {
        int c = wn * 32 + j * 8 + qc * 2;
        float b0 = bias[c], b1 = bias[c + 1];
        float s0 = 0.f, s1 = 0.f;
#pragma unroll
        for (int i = 0; i < 4; i++) {
            int r0 = m0 + wm * 64 + i * 16 + qr;
            if (r0 < NN)     { s0 += tanhf(acc[i][j][0] + b0); s1 += tanhf(acc[i][j][1] + b1); }
            if (r0 + 8 < NN) { s0 += tanhf(acc[i][j][2] + b0); s1 += tanhf(acc[i][j][3] + b1); }
        }
        atomicAdd(&cs[c], s0);
        atomicAdd(&cs[c + 1], s1);
    }
    __syncthreads();
    if (t < HID) atomicAdd(&g_colsum[meta][t], cs[t]);
}

// ---------------- attention dot products ----------------
__global__ void k_attdot(const float* __restrict__ s0, const float* __restrict__ d0,
                         const float* __restrict__ s1, const float* __restrict__ d1) {
    int i = blockIdx.x * blockDim.x + threadIdx.x;   // n*8 + h
    if (i >= NN * HEADS) return;
    int h = i & 7;
    const float* xp = g_xp + (size_t)i * 16;
    float r0 = 0.f, r1 = 0.f, r2 = 0.f, r3 = 0.f;
#pragma unroll
    for (int d = 0; d < 16; d++) {
        float xv = xp[d];
        r0 += xv * s0[h * 16 + d];
        r1 += xv * d0[h * 16 + d];
        r2 += xv * s1[h * 16 + d];
        r3 += xv * d1[h * 16 + d];
    }
    g_asrc[0][i] = r0; g_adst[0][i] = r1;
    g_asrc[1][i] = r2; g_adst[1][i] = r3;
}

// ---------------- CSR build (scalar, proven config) ----------------
__global__ void k_deg(const int* __restrict__ e0, const int* __restrict__ e1) {
    int i = blockIdx.x * blockDim.x + threadIdx.x;
    if (i >= EE) return;
    int m = blockIdx.y;
    const int* ei = m ? e1 : e0;
    atomicAdd(&g_deg[m][ei[EE + i]], 1);
}

// ---- 3-phase parallel scan over g_deg -> g_rowptr/g_cursor ----
// Phase 1: per-block (2048 elems) local exclusive prefix + block total.
__global__ __launch_bounds__(256) void k_scan1() {
    int m = blockIdx.y, b = blockIdx.x, t = threadIdx.x;
    int base = b * 2048 + t * 8;
    int v[8];
    int s = 0;
#pragma unroll
    for (int i = 0; i < 8; i++) {
        v[i] = (base + i < NN) ? g_deg[m][base + i] : 0;
        s += v[i];
    }
    __shared__ int sh[256];
    sh[t] = s;
    __syncthreads();
#pragma unroll
    for (int off = 1; off < 256; off <<= 1) {
        int x = (t >= off) ? sh[t - off] : 0;
        __syncthreads();
        sh[t] += x;
        __syncthreads();
    }
    int run = (t == 0) ? 0 : sh[t - 1];
    if (t == 255) g_bsum[m][b] = sh[255];
#pragma unroll
    for (int i = 0; i < 8; i++) {
        if (base + i < NN) g_rowptr[m][base + i] = run;
        run += v[i];
    }
}

// Phase 2: warp-scan the 25 block totals (one warp per metapath).
__global__ void k_scan2() {
    int m = blockIdx.x, t = threadIdx.x;   // 32 threads
    int v = (t < SCAN_BLKS) ? g_bsum[m][t] : 0;
    int orig = v;
#pragma unroll
    for (int off = 1; off < 32; off <<= 1) {
        int x = __shfl_up_sync(0xffffffffu, v, off);
        if (t >= off) v += x;
    }
    if (t < SCAN_BLKS) g_bsum[m][t] = v - orig;   // exclusive
    if (t == SCAN_BLKS - 1) g_rowptr[m][NN] = v;  // total
}

// Phase 3: add block offsets; write final rowptr + cursor.
__global__ __launch_bounds__(256) void k_scan3() {
    int m = blockIdx.y, b = blockIdx.x, t = threadIdx.x;
    int off = g_bsum[m][b];
    int base = b * 2048 + t * 8;
#pragma unroll
    for (int i = 0; i < 8; i++) {
        int idx = base + i;
        if (idx < NN) {
            int r = g_rowptr[m][idx] + off;
            g_rowptr[m][idx] = r;
            g_cursor[m][idx] = r;
        }
    }
}

__global__ void k_fill(const int* __restrict__ e0, const int* __restrict__ e1) {
    int i = blockIdx.x * blockDim.x + threadIdx.x;
    if (i >= EE) return;
    int m = blockIdx.y;
    const int* ei = m ? e1 : e0;
    int s = ei[i], d = ei[EE + i];
    int pos = atomicAdd(&g_cursor[m][d], 1);
    g_csr[m][pos] = s;
}

// ---------------- fused softmax + aggregation (fp16 gather, 2x unroll, proven) ----------------
__global__ __launch_bounds__(256) void k_agg() {
    int warp = (blockIdx.x * blockDim.x + threadIdx.x) >> 5;
    if (warp >= NN) return;
    int m = blockIdx.y;
    int lane = threadIdx.x & 31;
    int h = lane >> 2;
    int n = warp;
    float adst = g_adst[m][n * 8 + h];
    const float* __restrict__ asrc = g_asrc[m];
    const int* __restrict__ csr = g_csr[m];
    const uint2* __restrict__ xph = (const uint2*)g_xph;  // row stride = 32 uint2
    int j = g_rowptr[m][n], j1 = g_rowptr[m][n + 1];
    float ax = 0.f, ay = 0.f, az = 0.f, aw = 0.f, den = 0.f;
    for (; j + 1 < j1; j += 2) {
        int s0 = csr[j], s1 = csr[j + 1];
        float al0 = asrc[s0 * 8 + h] + adst;
        float al1 = asrc[s1 * 8 + h] + adst;
        uint2 u0 = xph[s0 * 32 + lane];
        uint2 u1 = xph[s1 * 32 + lane];
        al0 = (al0 > 0.f) ? al0 : 0.2f * al0;
        al1 = (al1 > 0.f) ? al1 : 0.2f * al1;
        float e0 = __expf(al0), e1 = __expf(al1);
        float2 f00 = __half22float2(*(__half2*)&u0.x);
        float2 f01 = __half22float2(*(__half2*)&u0.y);
        float2 f10 = __half22float2(*(__half2*)&u1.x);
        float2 f11 = __half22float2(*(__half2*)&u1.y);
        ax += e0 * f00.x; ay += e0 * f00.y; az += e0 * f01.x; aw += e0 * f01.y; den += e0;
        ax += e1 * f10.x; ay += e1 * f10.y; az += e1 * f11.x; aw += e1 * f11.y; den += e1;
    }
    if (j < j1) {
        int s0 = csr[j];
        float al0 = asrc[s0 * 8 + h] + adst;
        uint2 u0 = xph[s0 * 32 + lane];
        al0 = (al0 > 0.f) ? al0 : 0.2f * al0;
        float e0 = __expf(al0);
        float2 f00 = __half22float2(*(__half2*)&u0.x);
        float2 f01 = __half22float2(*(__half2*)&u0.y);
        ax += e0 * f00.x; ay += e0 * f00.y; az += e0 * f01.x; aw += e0 * f01.y; den += e0;
    }
    float inv = 1.f / (den + 1e-16f);
    float4 r;
    r.x = fmaxf(ax * inv, 0.f);
    r.y = fmaxf(ay * inv, 0.f);
    r.z = fmaxf(az * inv, 0.f);
    r.w = fmaxf(aw * inv, 0.f);
    *(float4*)(g_outm[m] + (size_t)n * HID + lane * 4) = r;
}

// ---------------- semantic softmax (beta) ----------------
__global__ void k_sem(const float* __restrict__ q) {
    __shared__ float s0[128], s1[128];
    int t = threadIdx.x;
    float qt = q[t];
    s0[t] = g_colsum[0][t] * (1.f / NN) * qt;
    s1[t] = g_colsum[1][t] * (1.f / NN) * qt;
    __syncthreads();
    for (int off = 64; off; off >>= 1) {
        if (t < off) { s0[t] += s0[t + off]; s1[t] += s1[t + off]; }
        __syncthreads();
    }
    if (t == 0) {
        float a = s0[0], b = s1[0];
        float mx = fmaxf(a, b);
        float ea = __expf(a - mx), eb = __expf(b - mx);
        float inv = 1.f / (ea + eb);
        g_beta[0] = ea * inv;
        g_beta[1] = eb * inv;
    }
}

// ---------------- final head ----------------
__global__ __launch_bounds__(256) void k_final(const float* __restrict__ Wl,
                                               const float* __restrict__ bl,
                                               float* __restrict__ out) {
    int warp = (blockIdx.x * blockDim.x + threadIdx.x) >> 5;
    if (warp >= NN) return;
    int lane = threadIdx.x & 31;
    float b0 = g_beta[0], b1 = g_beta[1];
    float p0 = 0.f, p1 = 0.f, p2 = 0.f;
#pragma unroll
    for (int r = 0; r < 4; r++) {
        int c = lane + r * 32;
        float f = b0 * g_outm[0][(size_t)warp * HID + c] + b1 * g_outm[1][(size_t)warp * HID + c];
        p0 += f * Wl[c * 3 + 0];
        p1 += f * Wl[c * 3 + 1];
        p2 += f * Wl[c * 3 + 2];
    }
#pragma unroll
    for (int off = 16; off; off >>= 1) {
        p0 += __shfl_down_sync(0xffffffffu, p0, off);
        p1 += __shfl_down_sync(0xffffffffu, p1, off);
        p2 += __shfl_down_sync(0xffffffffu, p2, off);
    }
    if (lane == 0) {
        out[warp * 3 + 0] = p0 + bl[0];
        out[warp * 3 + 1] = p1 + bl[1];
        out[warp * 3 + 2] = p2 + bl[2];
    }
}

// ---------------- launch ----------------
extern "C" void kernel_launch(void* const* d_in, const int* in_sizes, int n_in,
                              void* d_out, int out_size) {
    const float* x      = (const float*)d_in[0];
    const int*   e0     = (const int*)d_in[1];
    const int*   e1     = (const int*)d_in[2];
    const float* W_proj = (const float*)d_in[3];
    const float* b_proj = (const float*)d_in[4];
    const float* as0    = (const float*)d_in[5];
    const float* ad0    = (const float*)d_in[6];
    const float* as1    = (const float*)d_in[7];
    const float* ad1    = (const float*)d_in[8];
    const float* Wk     = (const float*)d_in[9];
    const float* bk     = (const float*)d_in[10];
    const float* q      = (const float*)d_in[11];
    const float* W_lin  = (const float*)d_in[12];
    const float* b_lin  = (const float*)d_in[13];
    float* out = (float*)d_out;

    static void* p_deg = nullptr;
    static void* p_colsum = nullptr;
    if (!p_deg) {
        cudaGetSymbolAddress(&p_deg, g_deg);
        cudaGetSymbolAddress(&p_colsum, g_colsum);
        cudaFuncSetAttribute(k_gemm_proj, cudaFuncAttributeMaxDynamicSharedMemorySize, PROJ_SMEM);
    }

    cudaMemsetAsync(p_deg, 0, 2 * NN * sizeof(int), 0);
    cudaMemsetAsync(p_colsum, 0, 2 * HID * sizeof(float), 0);

    k_gemm_proj<<<(NN + 127) / 128, 256, PROJ_SMEM>>>(x, W_proj, b_proj);
    k_attdot<<<(NN * HEADS + 255) / 256, 256>>>(as0, ad0, as1, ad1);
    dim3 ge((EE + 255) / 256, 2);
    k_deg<<<ge, 256>>>(e0, e1);
    k_scan1<<<dim3(SCAN_BLKS, 2), 256>>>();
    k_scan2<<<2, 32>>>();
    k_scan3<<<dim3(SCAN_BLKS, 2), 256>>>();
    k_fill<<<ge, 256>>>(e0, e1);
    k_agg<<<dim3((NN + 7) / 8, 2), 256>>>();
    k_gemm_tanh<<<dim3((NN + 127) / 128, 2), 256>>>(Wk, bk);
    k_sem<<<1, 128>>>(q);
    k_final<<<(NN + 7) / 8, 256>>>(W_lin, b_lin, out);
}